// round 6
// baseline (speedup 1.0000x reference)
#include <cuda_runtime.h>

// Problem constants (fixed by the dataset)
#define NB 1024
#define NM 8192
#define NN 32
#define NS 128

// Tiling
#define BT 128                         // b rows per block
#define MC 16                          // m per chunk
#define MSPLIT 32                      // blocks along m
#define NCHUNK ((NM / MC) / MSPLIT)    // 16 chunks per block
#define NTHREADS 256

// Scratch (no allocation allowed -> device globals)
__device__ float  g_kv[2 * NN * NM];          // [64][M]: rows 0..31 = z_j^T, 32..63 = b_unit^T
__device__ float4 g_par0[NM];                 // {w_perp, w_perp*|z_j|^2, -2*w_perp, w_diff}
__device__ float2 g_par1[NM];                 // {c = z_j.b_unit, alpha}
__device__ float  g_zn[NB];                   // |z_b|^2
__device__ float  g_part[MSPLIT * NB * NS];   // 16 MB partial outputs

__global__ void pre_z_kernel(const float* __restrict__ z) {
    int b = blockIdx.x * blockDim.x + threadIdx.x;
    if (b >= NB) return;
    const float4* z4 = reinterpret_cast<const float4*>(z + b * NN);
    float s = 0.f;
    #pragma unroll
    for (int i = 0; i < NN / 4; i++) {
        float4 v = z4[i];
        s = fmaf(v.x, v.x, s); s = fmaf(v.y, v.y, s);
        s = fmaf(v.z, v.z, s); s = fmaf(v.w, v.w, s);
    }
    g_zn[b] = s;
}

__global__ void pre_m_kernel(const float* __restrict__ zj, const float* __restrict__ vd,
                             const float* __restrict__ alpha, const float* __restrict__ sp,
                             const float* __restrict__ spr) {
    int m = blockIdx.x * blockDim.x + threadIdx.x;
    if (m >= NM) return;
    const float4* z4 = reinterpret_cast<const float4*>(zj + m * NN);
    const float4* d4 = reinterpret_cast<const float4*>(vd + m * NN);
    float d2 = 0.f, zz = 0.f, cr = 0.f;
    #pragma unroll
    for (int i = 0; i < NN / 4; i++) {
        float4 d = d4[i], zv = z4[i];
        d2 = fmaf(d.x, d.x, d2);  d2 = fmaf(d.y, d.y, d2);
        d2 = fmaf(d.z, d.z, d2);  d2 = fmaf(d.w, d.w, d2);
        zz = fmaf(zv.x, zv.x, zz); zz = fmaf(zv.y, zv.y, zz);
        zz = fmaf(zv.z, zv.z, zz); zz = fmaf(zv.w, zv.w, zz);
        cr = fmaf(zv.x, d.x, cr);  cr = fmaf(zv.y, d.y, cr);
        cr = fmaf(zv.z, d.z, cr);  cr = fmaf(zv.w, d.w, cr);
    }
    float dn  = sqrtf(d2);
    float inv = (dn > 1e-6f) ? (1.0f / dn) : 0.0f;   // EPS = 1e-6, strict >
    // Transposed writes: warp lanes are consecutive m -> coalesced per row k
    #pragma unroll
    for (int i = 0; i < NN / 4; i++) {
        float4 d = d4[i], zv = z4[i];
        g_kv[(4 * i + 0) * NM + m] = zv.x;
        g_kv[(4 * i + 1) * NM + m] = zv.y;
        g_kv[(4 * i + 2) * NM + m] = zv.z;
        g_kv[(4 * i + 3) * NM + m] = zv.w;
        g_kv[(NN + 4 * i + 0) * NM + m] = d.x * inv;
        g_kv[(NN + 4 * i + 1) * NM + m] = d.y * inv;
        g_kv[(NN + 4 * i + 2) * NM + m] = d.z * inv;
        g_kv[(NN + 4 * i + 3) * NM + m] = d.w * inv;
    }
    const float tiny = 1.1920929e-7f;   // float32 machine eps (jnp.finfo.eps)
    float a  = fmaxf(sp[m],  tiny);
    float bb = fmaxf(spr[m], tiny);
    float w_par  = 1.f / (a * a);
    float w_perp = 1.f / (bb * bb);
    g_par0[m] = make_float4(w_perp, w_perp * zz, -2.f * w_perp, w_par - w_perp);
    g_par1[m] = make_float2(cr * inv, alpha[m]);
}

__global__ void __launch_bounds__(NTHREADS, 2)
fused_kernel(const float* __restrict__ z, const float* __restrict__ that) {
    __shared__ float z_t[NN][BT];        // 16 KB, z transposed: [k][b]
    __shared__ float zn_sh[BT];          // 0.5 KB
    __shared__ float kv_sh[2 * NN][MC];  // 4 KB, [k][m] (rows 0..31 z_j, 32..63 b_unit)
    __shared__ float gain_sh[MC][BT];    // 8 KB
    __shared__ float that_sh[MC][NS];    // 8 KB

    const int tid    = threadIdx.x;
    const int b_base = blockIdx.x * BT;
    const int ms     = blockIdx.y;

    // Load z tile transposed (one-time)
    for (int idx = tid; idx < BT * NN; idx += NTHREADS) {
        int bb = idx >> 5, k = idx & 31;
        z_t[k][bb] = z[(b_base + bb) * NN + k];
    }
    if (tid < BT) zn_sh[tid] = g_zn[b_base + tid];

    // Phase-1 mapping: 4 b x 2 m per thread (warp = 32 b-quads, same m-pair -> kv broadcast)
    const int bq  = tid & 31;
    const int mp  = tid >> 5;
    const int b0  = bq * 4;
    const int m0  = mp * 2;
    // Phase-2 mapping: 8 b x 8 s register tile
    const int sx  = tid & 15;
    const int byy = tid >> 4;
    const int s0  = sx * 8;
    const int pb0 = byy * 8;

    unsigned long long acc[8][4];        // 8 b-rows x 4 f32x2 pairs (8 s)
    #pragma unroll
    for (int i = 0; i < 8; i++)
        #pragma unroll
        for (int j = 0; j < 4; j++) acc[i][j] = 0ull;

    const int chunk0 = ms * NCHUNK;
    for (int ch = 0; ch < NCHUNK; ch++) {
        const int mbase = (chunk0 + ch) * MC;
        __syncthreads();   // previous chunk's readers done before overwriting smem

        // Cooperative load kv chunk: 64 x 16 floats = 256 float4, one per thread
        {
            int k = tid >> 2, mq = tid & 3;
            reinterpret_cast<float4*>(&kv_sh[k][0])[mq] =
                __ldg(reinterpret_cast<const float4*>(g_kv + k * NM + mbase) + mq);
        }
        // Cooperative load T_hat chunk: 16 x 128 floats = 512 float4, two per thread
        #pragma unroll
        for (int t = 0; t < 2; t++) {
            int f  = tid + t * NTHREADS;
            int mm = f >> 5, sq = f & 31;
            reinterpret_cast<float4*>(&that_sh[mm][0])[sq] =
                __ldg(reinterpret_cast<const float4*>(that + (size_t)(mbase + mm) * NS) + sq);
        }
        __syncthreads();

        // ---- Phase 1: gains for this chunk (two dots per pair, f32x2 over m-pair) ----
        {
            unsigned long long u2[4], v2[4];
            #pragma unroll
            for (int i = 0; i < 4; i++) { u2[i] = 0ull; v2[i] = 0ull; }
            #pragma unroll
            for (int k = 0; k < NN; k++) {
                float4 z4 = *reinterpret_cast<const float4*>(&z_t[k][b0]);
                unsigned long long zj2 = *reinterpret_cast<const unsigned long long*>(&kv_sh[k][m0]);
                unsigned long long bv2 = *reinterpret_cast<const unsigned long long*>(&kv_sh[NN + k][m0]);
                const float zf[4] = {z4.x, z4.y, z4.z, z4.w};
                #pragma unroll
                for (int i = 0; i < 4; i++) {
                    unsigned long long zd;
                    asm("mov.b64 %0, {%1, %1};" : "=l"(zd) : "r"(__float_as_uint(zf[i])));
                    asm("fma.rn.f32x2 %0, %1, %2, %0;" : "+l"(u2[i]) : "l"(zd), "l"(zj2));
                    asm("fma.rn.f32x2 %0, %1, %2, %0;" : "+l"(v2[i]) : "l"(zd), "l"(bv2));
                }
            }
            float4 pA = g_par0[mbase + m0];
            float4 pB = g_par0[mbase + m0 + 1];
            float2 cA = g_par1[mbase + m0];
            float2 cB = g_par1[mbase + m0 + 1];
            float4 gOutA, gOutB;
            float* gA = &gOutA.x;
            float* gB = &gOutB.x;
            #pragma unroll
            for (int i = 0; i < 4; i++) {
                float ua, ub, va, vb;
                asm("mov.b64 {%0, %1}, %2;" : "=f"(ua), "=f"(ub) : "l"(u2[i]));
                asm("mov.b64 {%0, %1}, %2;" : "=f"(va), "=f"(vb) : "l"(v2[i]));
                float znb = zn_sh[b0 + i];
                // q = w_perp*|z|^2 + w_perp*|zj|^2 - 2*w_perp*(z.zj) + w_diff*(z.b - c)^2
                float ta = va - cA.x;
                float qa = fmaf(pA.x, znb, pA.y);
                qa = fmaf(pA.z, ua, qa);
                qa = fmaf(pA.w * ta, ta, qa);
                qa = fminf(qa, 25.f);
                gA[i] = cA.y * __expf(-3.14159265358979323846f * qa);
                float tb = vb - cB.x;
                float qb = fmaf(pB.x, znb, pB.y);
                qb = fmaf(pB.z, ub, qb);
                qb = fmaf(pB.w * tb, tb, qb);
                qb = fminf(qb, 25.f);
                gB[i] = cB.y * __expf(-3.14159265358979323846f * qb);
            }
            *reinterpret_cast<float4*>(&gain_sh[m0][b0])     = gOutA;
            *reinterpret_cast<float4*>(&gain_sh[m0 + 1][b0]) = gOutB;
        }
        __syncthreads();

        // ---- Phase 2: acc[8b][8s] += gain[8b][mc] * that[mc][8s]  (f32x2 over s) ----
        #pragma unroll
        for (int mc = 0; mc < MC; mc++) {
            float4 ga = *reinterpret_cast<const float4*>(&gain_sh[mc][pb0]);
            float4 gb = *reinterpret_cast<const float4*>(&gain_sh[mc][pb0 + 4]);
            ulonglong2 tlo = *reinterpret_cast<const ulonglong2*>(&that_sh[mc][s0]);
            ulonglong2 thi = *reinterpret_cast<const ulonglong2*>(&that_sh[mc][s0 + 4]);
            unsigned long long t2[4] = {tlo.x, tlo.y, thi.x, thi.y};
            const float gsc[8] = {ga.x, ga.y, ga.z, ga.w, gb.x, gb.y, gb.z, gb.w};
            #pragma unroll
            for (int i = 0; i < 8; i++) {
                unsigned long long gd;
                asm("mov.b64 %0, {%1, %1};" : "=l"(gd) : "r"(__float_as_uint(gsc[i])));
                #pragma unroll
                for (int j = 0; j < 4; j++)
                    asm("fma.rn.f32x2 %0, %1, %2, %0;" : "+l"(acc[i][j]) : "l"(gd), "l"(t2[j]));
            }
        }
    }

    // Flush accumulators to partial buffer (fully written across grid)
    float* outp = g_part + (size_t)ms * (NB * NS) + (size_t)(b_base + pb0) * NS + s0;
    #pragma unroll
    for (int i = 0; i < 8; i++) {
        float2 f0 = *reinterpret_cast<float2*>(&acc[i][0]);
        float2 f1 = *reinterpret_cast<float2*>(&acc[i][1]);
        float2 f2 = *reinterpret_cast<float2*>(&acc[i][2]);
        float2 f3 = *reinterpret_cast<float2*>(&acc[i][3]);
        *reinterpret_cast<float4*>(outp + (size_t)i * NS)     = make_float4(f0.x, f0.y, f1.x, f1.y);
        *reinterpret_cast<float4*>(outp + (size_t)i * NS + 4) = make_float4(f2.x, f2.y, f3.x, f3.y);
    }
}

__global__ void reduce_kernel(float* __restrict__ out) {
    int idx = blockIdx.x * blockDim.x + threadIdx.x;   // 0 .. B*S/4-1
    const float4* gp = reinterpret_cast<const float4*>(g_part);
    float4 a = make_float4(0.f, 0.f, 0.f, 0.f);
    #pragma unroll
    for (int p = 0; p < MSPLIT; p++) {
        float4 v = gp[(size_t)p * (NB * NS / 4) + idx];
        a.x += v.x; a.y += v.y; a.z += v.z; a.w += v.w;
    }
    reinterpret_cast<float4*>(out)[idx] = a;
}

extern "C" void kernel_launch(void* const* d_in, const int* in_sizes, int n_in,
                              void* d_out, int out_size) {
    const float* z     = (const float*)d_in[0];   // [B, N]
    const float* zj    = (const float*)d_in[1];   // [M, N]
    const float* vd    = (const float*)d_in[2];   // [M, N]
    const float* that  = (const float*)d_in[3];   // [M, S]
    const float* alpha = (const float*)d_in[4];   // [M]
    const float* sp    = (const float*)d_in[5];   // [M]
    const float* spr   = (const float*)d_in[6];   // [M]
    float* out = (float*)d_out;                   // [B, S] fp32

    pre_z_kernel<<<(NB + 255) / 256, 256>>>(z);
    pre_m_kernel<<<(NM + 255) / 256, 256>>>(zj, vd, alpha, sp, spr);
    fused_kernel<<<dim3(NB / BT, MSPLIT), NTHREADS>>>(z, that);
    reduce_kernel<<<(NB * NS / 4 + 255) / 256, 256>>>(out);
}